// round 10
// baseline (speedup 1.0000x reference)
#include <cuda_runtime.h>
#include <cuda_fp16.h>

#define NN 100000
#define EE 1200000
#define HID 64
#define NG 256
#define OC 10
#define IN0 7

// ---- scratch (static device globals) ----
__device__ int   g_cnti[NN];
__device__ int   g_rowp[NN];
__device__ int   g_cursor[NN];
__device__ int   g_total;
__device__ uint2 g_edge[EE];                  // packed {src, wgt-bits}
__device__ float g_dis[NN];
__device__ __align__(32)  float  g_xp[NN * 8];     // x padded to 8ch
__device__ __align__(256) __half g_hw1[NN * HID];  // layer-1 hw (fp16)
__device__ __align__(256) __half g_hw2[NN * HID];  // layer-2 hw (fp16)
__device__ float g_agg[NN * HID];
__device__ float g_sums[NG * HID];
__device__ float g_gcnt[NG];

// ---- zero counters + pad x to 8 channels ----
__global__ void k_zero(const float* __restrict__ x) {
    int i = blockIdx.x * blockDim.x + threadIdx.x;
    if (i < NN) {
        g_cnti[i] = 0;
        const float* xr = x + (long long)i * IN0;
        float4 a, b;
        a.x = xr[0]; a.y = xr[1]; a.z = xr[2]; a.w = xr[3];
        b.x = xr[4]; b.y = xr[5]; b.z = xr[6]; b.w = 0.0f;
        ((float4*)(g_xp + (long long)i * 8))[0] = a;
        ((float4*)(g_xp + (long long)i * 8))[1] = b;
    }
    if (i < NG * HID) g_sums[i] = 0.0f;
    if (i < NG) g_gcnt[i] = 0.0f;
    if (i == 0) g_total = 0;
}

// ---- histogram on dst, 4 edges/thread for MLP ----
__global__ void k_hist(const int* __restrict__ ei) {
    int e4 = (blockIdx.x * blockDim.x + threadIdx.x) * 4;
    if (e4 >= EE) return;
    int4 d = *(const int4*)&ei[EE + e4];   // EE % 4 == 0 -> aligned
    atomicAdd(&g_cnti[d.x], 1);
    atomicAdd(&g_cnti[d.y], 1);
    atomicAdd(&g_cnti[d.z], 1);
    atomicAdd(&g_cnti[d.w], 1);
}

// ---- fused scan: per-block local scan + atomic base claim ----
__global__ void k_scanA() {
    __shared__ int sm[256];
    __shared__ int base_sm;
    int t = threadIdx.x;
    int i = blockIdx.x * 256 + t;
    int v = (i < NN) ? g_cnti[i] : 0;
    sm[t] = v;
    __syncthreads();
#pragma unroll
    for (int off = 1; off < 256; off <<= 1) {
        int add = (t >= off) ? sm[t - off] : 0;
        __syncthreads();
        sm[t] += add;
        __syncthreads();
    }
    if (t == 255) base_sm = atomicAdd(&g_total, sm[255]);
    __syncthreads();
    if (i < NN) {
        int r = base_sm + sm[t] - v;
        g_rowp[i] = r;
        g_cursor[i] = r;
        g_dis[i] = rsqrtf((float)v + 1.0f);
    }
}

// ---- fill CSR, 4 edges/thread for MLP ----
__global__ void k_fill(const int* __restrict__ ei) {
    int e4 = (blockIdx.x * blockDim.x + threadIdx.x) * 4;
    if (e4 >= EE) return;
    int4 s = *(const int4*)&ei[e4];
    int4 d = *(const int4*)&ei[EE + e4];
    int p0 = atomicAdd(&g_cursor[d.x], 1);
    int p1 = atomicAdd(&g_cursor[d.y], 1);
    int p2 = atomicAdd(&g_cursor[d.z], 1);
    int p3 = atomicAdd(&g_cursor[d.w], 1);
    g_edge[p0] = make_uint2((unsigned)s.x, __float_as_uint(g_dis[s.x] * g_dis[d.x]));
    g_edge[p1] = make_uint2((unsigned)s.y, __float_as_uint(g_dis[s.y] * g_dis[d.y]));
    g_edge[p2] = make_uint2((unsigned)s.z, __float_as_uint(g_dis[s.z] * g_dis[d.z]));
    g_edge[p3] = make_uint2((unsigned)s.w, __float_as_uint(g_dis[s.w] * g_dis[d.w]));
}

// ---- helpers ----
__device__ __forceinline__ void unpack8(uint4 u, float* f) {
    const __half2* h = (const __half2*)&u;
#pragma unroll
    for (int j = 0; j < 4; j++) {
        float2 p = __half22float2(h[j]);
        f[2 * j] = p.x;
        f[2 * j + 1] = p.y;
    }
}
__device__ __forceinline__ uint4 pack8(const float* s) {
    __half2 p0 = __floats2half2_rn(s[0], s[1]);
    __half2 p1 = __floats2half2_rn(s[2], s[3]);
    __half2 p2 = __floats2half2_rn(s[4], s[5]);
    __half2 p3 = __floats2half2_rn(s[6], s[7]);
    uint4 o;
    o.x = *(unsigned*)&p0; o.y = *(unsigned*)&p1;
    o.z = *(unsigned*)&p2; o.w = *(unsigned*)&p3;
    return o;
}

// ---- fuse0: gather7 + mm7(+b0) + relu + mm64(W1) -> hw1 (fp16) ----
// 256 threads = 32 nodes x 8 threads (q = channel octet).
// Smem consumers all sit AFTER a __syncthreads() covering the loads.
__global__ void __launch_bounds__(256) k_fuse0(const float* __restrict__ W0,
                                               const float* __restrict__ b0,
                                               const float* __restrict__ W1) {
    __shared__ float W1s[HID * HID];   // 16 KB
    __shared__ float W0s[IN0 * HID];   // 1792 B
    __shared__ float b0s[HID];
    __shared__ float xs[32][8];
    __shared__ float h1[32][HID];      // 8 KB
    int t = threadIdx.x;
    for (int i = t; i < HID * HID / 4; i += 256)
        ((float4*)W1s)[i] = ((const float4*)W1)[i];
    if (t < IN0 * 16) ((float4*)W0s)[t] = ((const float4*)W0)[t];
    if (t < 16) ((float4*)b0s)[t] = ((const float4*)b0)[t];
    int nl = t >> 3, q = t & 7;
    int n = blockIdx.x * 32 + nl;
    // gather phase: channel q of node n over padded x (no smem reads here)
    float acc0 = 0.0f, acc1 = 0.0f;
    if (n < NN) {
        int s0 = g_rowp[n], deg = g_cnti[n];
        float d = g_dis[n];
        acc0 = d * d * g_xp[(long long)n * 8 + q];
        int e = s0, end = s0 + deg;
        for (; e + 1 < end; e += 2) {
            uint2 ea = g_edge[e], eb = g_edge[e + 1];
            acc0 += __uint_as_float(ea.y) * g_xp[(long long)ea.x * 8 + q];
            acc1 += __uint_as_float(eb.y) * g_xp[(long long)eb.x * 8 + q];
        }
        if (e < end) {
            uint2 ea = g_edge[e];
            acc0 += __uint_as_float(ea.y) * g_xp[(long long)ea.x * 8 + q];
        }
    }
    xs[nl][q] = acc0 + acc1;
    __syncthreads();   // covers xs AND W0s/b0s/W1s loads
    // mm7 + bias + relu -> h1
    {
        float s[8];
#pragma unroll
        for (int i = 0; i < 8; i++) s[i] = b0s[q * 8 + i];
#pragma unroll
        for (int k = 0; k < IN0; k++) {
            float hv = xs[nl][k];
#pragma unroll
            for (int i = 0; i < 8; i++) s[i] += hv * W0s[k * HID + q * 8 + i];
        }
#pragma unroll
        for (int i = 0; i < 8; i++) h1[nl][q * 8 + i] = fmaxf(s[i], 0.0f);
    }
    __syncthreads();
    // mm64 (W1) -> hw1 fp16
    if (n < NN) {
        float s[8];
#pragma unroll
        for (int i = 0; i < 8; i++) s[i] = 0.0f;
        for (int k = 0; k < HID; k++) {
            float hv = h1[nl][k];
#pragma unroll
            for (int i = 0; i < 8; i++) s[i] += hv * W1s[k * HID + q * 8 + i];
        }
        ((uint4*)(g_hw1 + (long long)n * HID))[q] = pack8(s);
    }
}

// ---- fuse1: gather64(hw1,+b1) + relu + mm64(W2) -> hw2 (fp16) ----
__global__ void __launch_bounds__(256) k_fuse1(const float* __restrict__ b1,
                                               const float* __restrict__ W2) {
    __shared__ float W2s[HID * HID];   // 16 KB
    __shared__ float b1s[HID];
    __shared__ float h[32][HID];       // 8 KB
    int t = threadIdx.x;
    for (int i = t; i < HID * HID / 4; i += 256)
        ((float4*)W2s)[i] = ((const float4*)W2)[i];
    if (t < 16) ((float4*)b1s)[t] = ((const float4*)b1)[t];
    __syncthreads();   // *** FIX: b1s is read in the gather phase below ***
    int nl = t >> 3, q = t & 7;
    int n = blockIdx.x * 32 + nl;
    float acc[8];
#pragma unroll
    for (int i = 0; i < 8; i++) acc[i] = 0.0f;
    if (n < NN) {
        int s0 = g_rowp[n], deg = g_cnti[n];
        float d = g_dis[n];
        float dd = d * d;
        float tmp[8];
        uint4 self = ((const uint4*)(g_hw1 + (long long)n * HID))[q];
        unpack8(self, tmp);
        float acc2[8];
#pragma unroll
        for (int i = 0; i < 8; i++) {
            acc[i] = dd * tmp[i] + b1s[q * 8 + i];
            acc2[i] = 0.0f;
        }
        int e = s0, end = s0 + deg;
        for (; e + 1 < end; e += 2) {
            uint2 e0 = g_edge[e], e1 = g_edge[e + 1];
            uint4 v0 = ((const uint4*)(g_hw1 + (long long)e0.x * HID))[q];
            uint4 v1 = ((const uint4*)(g_hw1 + (long long)e1.x * HID))[q];
            float f0[8], f1[8];
            unpack8(v0, f0); unpack8(v1, f1);
            float w0 = __uint_as_float(e0.y), w1 = __uint_as_float(e1.y);
#pragma unroll
            for (int i = 0; i < 8; i++) acc[i] += w0 * f0[i];
#pragma unroll
            for (int i = 0; i < 8; i++) acc2[i] += w1 * f1[i];
        }
        if (e < end) {
            uint2 e0 = g_edge[e];
            uint4 v0 = ((const uint4*)(g_hw1 + (long long)e0.x * HID))[q];
            float f0[8];
            unpack8(v0, f0);
            float w0 = __uint_as_float(e0.y);
#pragma unroll
            for (int i = 0; i < 8; i++) acc[i] += w0 * f0[i];
        }
#pragma unroll
        for (int i = 0; i < 8; i++) acc[i] += acc2[i];
    }
    // relu -> smem
#pragma unroll
    for (int i = 0; i < 8; i++) h[nl][q * 8 + i] = fmaxf(acc[i], 0.0f);
    __syncthreads();
    // mm64 (W2) -> hw2 fp16
    if (n < NN) {
        float s[8];
#pragma unroll
        for (int i = 0; i < 8; i++) s[i] = 0.0f;
        for (int k = 0; k < HID; k++) {
            float hv = h[nl][k];
#pragma unroll
            for (int i = 0; i < 8; i++) s[i] += hv * W2s[k * HID + q * 8 + i];
        }
        ((uint4*)(g_hw2 + (long long)n * HID))[q] = pack8(s);
    }
}

// ---- final gather: agg = Â hw2 + b2 (fp32 out for pool); no smem ----
__global__ void __launch_bounds__(256) k_gather_last(const float* __restrict__ b2) {
    int t = threadIdx.x;
    int n = blockIdx.x * 32 + (t >> 3);
    int q = t & 7;
    if (n >= NN) return;
    int s0 = g_rowp[n], deg = g_cnti[n];
    float d = g_dis[n];
    float dd = d * d;
    float acc[8], acc2[8], tmp[8];
    uint4 self = ((const uint4*)(g_hw2 + (long long)n * HID))[q];
    unpack8(self, tmp);
    float4 b0 = ((const float4*)b2)[q * 2];
    float4 b1 = ((const float4*)b2)[q * 2 + 1];
    acc[0] = dd * tmp[0] + b0.x; acc[1] = dd * tmp[1] + b0.y;
    acc[2] = dd * tmp[2] + b0.z; acc[3] = dd * tmp[3] + b0.w;
    acc[4] = dd * tmp[4] + b1.x; acc[5] = dd * tmp[5] + b1.y;
    acc[6] = dd * tmp[6] + b1.z; acc[7] = dd * tmp[7] + b1.w;
#pragma unroll
    for (int i = 0; i < 8; i++) acc2[i] = 0.0f;
    int e = s0, end = s0 + deg;
    for (; e + 1 < end; e += 2) {
        uint2 e0 = g_edge[e], e1 = g_edge[e + 1];
        uint4 v0 = ((const uint4*)(g_hw2 + (long long)e0.x * HID))[q];
        uint4 v1 = ((const uint4*)(g_hw2 + (long long)e1.x * HID))[q];
        float f0[8], f1[8];
        unpack8(v0, f0); unpack8(v1, f1);
        float w0 = __uint_as_float(e0.y), w1 = __uint_as_float(e1.y);
#pragma unroll
        for (int i = 0; i < 8; i++) acc[i] += w0 * f0[i];
#pragma unroll
        for (int i = 0; i < 8; i++) acc2[i] += w1 * f1[i];
    }
    if (e < end) {
        uint2 e0 = g_edge[e];
        uint4 v0 = ((const uint4*)(g_hw2 + (long long)e0.x * HID))[q];
        float f0[8];
        unpack8(v0, f0);
        float w0 = __uint_as_float(e0.y);
#pragma unroll
        for (int i = 0; i < 8; i++) acc[i] += w0 * f0[i];
    }
#pragma unroll
    for (int i = 0; i < 8; i++) acc[i] += acc2[i];
    float4* ap = (float4*)&g_agg[(long long)n * HID + q * 8];
    ap[0] = make_float4(acc[0], acc[1], acc[2], acc[3]);
    ap[1] = make_float4(acc[4], acc[5], acc[6], acc[7]);
}

// ---- global mean pool: batch sorted ----
#define NPB 256
__global__ void k_pool(const int* __restrict__ batch) {
    int c = threadIdx.x;          // 0..63
    int n0 = blockIdx.x * NPB;
    int n1 = min(n0 + NPB, NN);
    int cur_g = batch[n0];
    float acc = 0.0f, cnt = 0.0f;
    for (int n = n0; n < n1; n++) {
        int g = batch[n];
        if (g != cur_g) {
            atomicAdd(&g_sums[cur_g * HID + c], acc);
            if (c == 0) atomicAdd(&g_gcnt[cur_g], cnt);
            acc = 0.0f; cnt = 0.0f; cur_g = g;
        }
        acc += g_agg[(long long)n * HID + c];
        cnt += 1.0f;
    }
    atomicAdd(&g_sums[cur_g * HID + c], acc);
    if (c == 0) atomicAdd(&g_gcnt[cur_g], cnt);
}

// ---- final linear ----
__global__ void k_fin(const float* __restrict__ lw,
                      const float* __restrict__ lb,
                      float* __restrict__ out) {
    int g = threadIdx.x;
    if (g >= NG) return;
    float inv = 1.0f / fmaxf(g_gcnt[g], 1.0f);
    float acc[OC];
#pragma unroll
    for (int o = 0; o < OC; o++) acc[o] = lb[o];
    for (int k = 0; k < HID; k++) {
        float v = g_sums[g * HID + k] * inv;
#pragma unroll
        for (int o = 0; o < OC; o++) acc[o] += v * lw[k * OC + o];
    }
#pragma unroll
    for (int o = 0; o < OC; o++) out[g * OC + o] = acc[o];
}

extern "C" void kernel_launch(void* const* d_in, const int* in_sizes, int n_in,
                              void* d_out, int out_size) {
    const float* x   = (const float*)d_in[0];
    const int* ei    = (const int*)d_in[1];
    const int* bat   = (const int*)d_in[2];
    const float* W0  = (const float*)d_in[3];
    const float* b0  = (const float*)d_in[4];
    const float* W1  = (const float*)d_in[5];
    const float* b1  = (const float*)d_in[6];
    const float* W2  = (const float*)d_in[7];
    const float* b2  = (const float*)d_in[8];
    const float* lw  = (const float*)d_in[9];
    const float* lb  = (const float*)d_in[10];
    float* out       = (float*)d_out;

    const int TB = 256;
    int g32_grid = (NN + 31) / 32;
    int e4_grid = (EE / 4 + TB - 1) / TB;

    k_zero<<<(NN + TB - 1) / TB, TB>>>(x);
    k_hist<<<e4_grid, TB>>>(ei);
    k_scanA<<<(NN + 255) / 256, 256>>>();
    k_fill<<<e4_grid, TB>>>(ei);

    k_fuse0<<<g32_grid, TB>>>(W0, b0, W1);
    k_fuse1<<<g32_grid, TB>>>(b1, W2);
    k_gather_last<<<g32_grid, TB>>>(b2);

    k_pool<<<(NN + NPB - 1) / NPB, 64>>>(bat);
    k_fin<<<1, TB>>>(lw, lb, out);
}

// round 13
// speedup vs baseline: 1.6332x; 1.6332x over previous
#include <cuda_runtime.h>
#include <cuda_fp16.h>

#define NN 100000
#define EE 1200000
#define HID 64
#define NG 256
#define OC 10
#define IN0 7

// ---- scratch (static device globals) ----
__device__ int   g_cnti[NN];
__device__ int   g_rowp[NN];
__device__ int   g_cursor[NN];
__device__ int   g_total;
__device__ uint2 g_edge[EE];                      // packed {src, wgt-bits}
__device__ float g_dis[NN];
__device__ __align__(32)  float  g_xp[NN * 8];    // x padded to 8ch
__device__ __align__(256) __half g_hwh[NN * HID]; // fp16 hw buffer (reused)
__device__ float g_h[NN * HID];                   // fp32 hidden buffer (reused)
__device__ __align__(16) float g_sums[NG * HID];

// ---- zero + pad x to 8 channels ----
__global__ void k_zero(const float* __restrict__ x) {
    int i = blockIdx.x * blockDim.x + threadIdx.x;
    if (i < NN) {
        g_cnti[i] = 0;
        const float* xr = x + (long long)i * IN0;
        float4 a, b;
        a.x = xr[0]; a.y = xr[1]; a.z = xr[2]; a.w = xr[3];
        b.x = xr[4]; b.y = xr[5]; b.z = xr[6]; b.w = 0.0f;
        ((float4*)(g_xp + (long long)i * 8))[0] = a;
        ((float4*)(g_xp + (long long)i * 8))[1] = b;
    }
    if (i < NG * HID) g_sums[i] = 0.0f;
    if (i == 0) g_total = 0;
}

// ---- histogram on dst, 8 edges/thread ----
__global__ void k_hist(const int* __restrict__ ei) {
    int e8 = (blockIdx.x * blockDim.x + threadIdx.x) * 8;
    if (e8 >= EE) return;
    int4 d0 = *(const int4*)&ei[EE + e8];
    int4 d1 = *(const int4*)&ei[EE + e8 + 4];
    atomicAdd(&g_cnti[d0.x], 1); atomicAdd(&g_cnti[d0.y], 1);
    atomicAdd(&g_cnti[d0.z], 1); atomicAdd(&g_cnti[d0.w], 1);
    atomicAdd(&g_cnti[d1.x], 1); atomicAdd(&g_cnti[d1.y], 1);
    atomicAdd(&g_cnti[d1.z], 1); atomicAdd(&g_cnti[d1.w], 1);
}

// ---- fused scan: per-block local scan + atomic base claim ----
__global__ void k_scanA() {
    __shared__ int sm[256];
    __shared__ int base_sm;
    int t = threadIdx.x;
    int i = blockIdx.x * 256 + t;
    int v = (i < NN) ? g_cnti[i] : 0;
    sm[t] = v;
    __syncthreads();
#pragma unroll
    for (int off = 1; off < 256; off <<= 1) {
        int add = (t >= off) ? sm[t - off] : 0;
        __syncthreads();
        sm[t] += add;
        __syncthreads();
    }
    if (t == 255) base_sm = atomicAdd(&g_total, sm[255]);
    __syncthreads();
    if (i < NN) {
        int r = base_sm + sm[t] - v;
        g_rowp[i] = r;
        g_cursor[i] = r;
        g_dis[i] = rsqrtf((float)v + 1.0f);
    }
}

// ---- fill CSR, 8 edges/thread ----
__global__ void k_fill(const int* __restrict__ ei) {
    int e8 = (blockIdx.x * blockDim.x + threadIdx.x) * 8;
    if (e8 >= EE) return;
    int4 s0 = *(const int4*)&ei[e8];
    int4 s1 = *(const int4*)&ei[e8 + 4];
    int4 d0 = *(const int4*)&ei[EE + e8];
    int4 d1 = *(const int4*)&ei[EE + e8 + 4];
    int p0 = atomicAdd(&g_cursor[d0.x], 1);
    int p1 = atomicAdd(&g_cursor[d0.y], 1);
    int p2 = atomicAdd(&g_cursor[d0.z], 1);
    int p3 = atomicAdd(&g_cursor[d0.w], 1);
    int p4 = atomicAdd(&g_cursor[d1.x], 1);
    int p5 = atomicAdd(&g_cursor[d1.y], 1);
    int p6 = atomicAdd(&g_cursor[d1.z], 1);
    int p7 = atomicAdd(&g_cursor[d1.w], 1);
    g_edge[p0] = make_uint2((unsigned)s0.x, __float_as_uint(g_dis[s0.x] * g_dis[d0.x]));
    g_edge[p1] = make_uint2((unsigned)s0.y, __float_as_uint(g_dis[s0.y] * g_dis[d0.y]));
    g_edge[p2] = make_uint2((unsigned)s0.z, __float_as_uint(g_dis[s0.z] * g_dis[d0.z]));
    g_edge[p3] = make_uint2((unsigned)s0.w, __float_as_uint(g_dis[s0.w] * g_dis[d0.w]));
    g_edge[p4] = make_uint2((unsigned)s1.x, __float_as_uint(g_dis[s1.x] * g_dis[d1.x]));
    g_edge[p5] = make_uint2((unsigned)s1.y, __float_as_uint(g_dis[s1.y] * g_dis[d1.y]));
    g_edge[p6] = make_uint2((unsigned)s1.z, __float_as_uint(g_dis[s1.z] * g_dis[d1.z]));
    g_edge[p7] = make_uint2((unsigned)s1.w, __float_as_uint(g_dis[s1.w] * g_dis[d1.w]));
}

// ---- helpers ----
__device__ __forceinline__ void unpack8(uint4 u, float* f) {
    const __half2* h = (const __half2*)&u;
#pragma unroll
    for (int j = 0; j < 4; j++) {
        float2 p = __half22float2(h[j]);
        f[2 * j] = p.x;
        f[2 * j + 1] = p.y;
    }
}
__device__ __forceinline__ uint4 pack8(const float* s) {
    __half2 p0 = __floats2half2_rn(s[0], s[1]);
    __half2 p1 = __floats2half2_rn(s[2], s[3]);
    __half2 p2 = __floats2half2_rn(s[4], s[5]);
    __half2 p3 = __floats2half2_rn(s[6], s[7]);
    uint4 o;
    o.x = *(unsigned*)&p0; o.y = *(unsigned*)&p1;
    o.z = *(unsigned*)&p2; o.w = *(unsigned*)&p3;
    return o;
}

// ---- gm7: gather7 + mm7(+b0) -> g_h (fp32 64ch). Tiny post-barrier work. ----
__global__ void __launch_bounds__(256) k_gm7(const float* __restrict__ W0,
                                             const float* __restrict__ b0) {
    __shared__ float W0s[IN0 * HID];
    __shared__ float b0s[HID];
    __shared__ float xs[32][8];
    int t = threadIdx.x;
    if (t < IN0 * 16) ((float4*)W0s)[t] = ((const float4*)W0)[t];
    if (t < 16) ((float4*)b0s)[t] = ((const float4*)b0)[t];
    int nl = t >> 3, q = t & 7;
    int n = blockIdx.x * 32 + nl;
    float acc0 = 0.0f, acc1 = 0.0f;
    if (n < NN) {
        int s0 = g_rowp[n], deg = g_cnti[n];
        float d = g_dis[n];
        acc0 = d * d * g_xp[(long long)n * 8 + q];
        int e = s0, end = s0 + deg;
        for (; e + 1 < end; e += 2) {
            uint2 ea = g_edge[e], eb = g_edge[e + 1];
            acc0 += __uint_as_float(ea.y) * g_xp[(long long)ea.x * 8 + q];
            acc1 += __uint_as_float(eb.y) * g_xp[(long long)eb.x * 8 + q];
        }
        if (e < end) {
            uint2 ea = g_edge[e];
            acc0 += __uint_as_float(ea.y) * g_xp[(long long)ea.x * 8 + q];
        }
    }
    xs[nl][q] = acc0 + acc1;
    __syncthreads();
    if (n < NN) {
        float s[8];
#pragma unroll
        for (int i = 0; i < 8; i++) s[i] = b0s[q * 8 + i];
#pragma unroll
        for (int k = 0; k < IN0; k++) {
            float hv = xs[nl][k];
#pragma unroll
            for (int i = 0; i < 8; i++) s[i] += hv * W0s[k * HID + q * 8 + i];
        }
        float4* hp = (float4*)&g_h[(long long)n * HID + q * 8];
        hp[0] = make_float4(s[0], s[1], s[2], s[3]);
        hp[1] = make_float4(s[4], s[5], s[6], s[7]);
    }
}

// ---- mm64: g_hwh = fp16( relu(g_h) @ W ), 64 nodes/block ----
__global__ void k_mm64(const float* __restrict__ W) {
    __shared__ float4 Ws4[HID * 16];    // 16 KB loaded once per 64 nodes
    __shared__ float4 hs4[16 * 16];
    int t = threadIdx.x;
#pragma unroll
    for (int i = 0; i < 4; i++) Ws4[t + 256 * i] = ((const float4*)W)[t + 256 * i];
    int nl = t >> 4;
    int q = t & 15;
#pragma unroll
    for (int g = 0; g < 4; g++) {
        int node = blockIdx.x * 64 + g * 16 + nl;
        __syncthreads();                 // covers Ws4 (g=0) and hs4 reuse
        float4 v = make_float4(0.f, 0.f, 0.f, 0.f);
        if (node < NN) v = ((const float4*)&g_h[(long long)node * HID])[q];
        v.x = fmaxf(v.x, 0.f); v.y = fmaxf(v.y, 0.f);
        v.z = fmaxf(v.z, 0.f); v.w = fmaxf(v.w, 0.f);
        hs4[nl * 16 + q] = v;
        __syncthreads();
        if (node < NN) {
            const float* hrow = (const float*)&hs4[nl * 16];
            float s[4] = {0.f, 0.f, 0.f, 0.f};
            float4 sv = make_float4(0.f, 0.f, 0.f, 0.f);
            (void)s;
#pragma unroll
            for (int k = 0; k < HID; k++) {
                float hv = hrow[k];
                float4 w = Ws4[k * 16 + q];
                sv.x += hv * w.x; sv.y += hv * w.y; sv.z += hv * w.z; sv.w += hv * w.w;
            }
            __half2 h0 = __floats2half2_rn(sv.x, sv.y);
            __half2 h1 = __floats2half2_rn(sv.z, sv.w);
            uint2 o;
            o.x = *(unsigned*)&h0;
            o.y = *(unsigned*)&h1;
            ((uint2*)(g_hwh + (long long)node * HID))[q] = o;
        }
    }
}

// ---- gather64h: g_h = Â g_hwh + b (fp32), 8 threads/node ----
__global__ void __launch_bounds__(256) k_gather64h(const float* __restrict__ b) {
    int t = threadIdx.x;
    int n = blockIdx.x * 32 + (t >> 3);
    int q = t & 7;
    if (n >= NN) return;
    int s0 = g_rowp[n], deg = g_cnti[n];
    float d = g_dis[n];
    float dd = d * d;
    float acc[8], acc2[8], tmp[8];
    uint4 self = ((const uint4*)(g_hwh + (long long)n * HID))[q];
    unpack8(self, tmp);
    float4 b0 = ((const float4*)b)[q * 2];
    float4 b1 = ((const float4*)b)[q * 2 + 1];
    acc[0] = dd * tmp[0] + b0.x; acc[1] = dd * tmp[1] + b0.y;
    acc[2] = dd * tmp[2] + b0.z; acc[3] = dd * tmp[3] + b0.w;
    acc[4] = dd * tmp[4] + b1.x; acc[5] = dd * tmp[5] + b1.y;
    acc[6] = dd * tmp[6] + b1.z; acc[7] = dd * tmp[7] + b1.w;
#pragma unroll
    for (int i = 0; i < 8; i++) acc2[i] = 0.0f;
    int e = s0, end = s0 + deg;
    for (; e + 1 < end; e += 2) {
        uint2 e0 = g_edge[e], e1 = g_edge[e + 1];
        uint4 v0 = ((const uint4*)(g_hwh + (long long)e0.x * HID))[q];
        uint4 v1 = ((const uint4*)(g_hwh + (long long)e1.x * HID))[q];
        float f0[8], f1[8];
        unpack8(v0, f0); unpack8(v1, f1);
        float w0 = __uint_as_float(e0.y), w1 = __uint_as_float(e1.y);
#pragma unroll
        for (int i = 0; i < 8; i++) acc[i] += w0 * f0[i];
#pragma unroll
        for (int i = 0; i < 8; i++) acc2[i] += w1 * f1[i];
    }
    if (e < end) {
        uint2 e0 = g_edge[e];
        uint4 v0 = ((const uint4*)(g_hwh + (long long)e0.x * HID))[q];
        float f0[8];
        unpack8(v0, f0);
        float w0 = __uint_as_float(e0.y);
#pragma unroll
        for (int i = 0; i < 8; i++) acc[i] += w0 * f0[i];
    }
#pragma unroll
    for (int i = 0; i < 8; i++) acc[i] += acc2[i];
    float4* hp = (float4*)&g_h[(long long)n * HID + q * 8];
    hp[0] = make_float4(acc[0], acc[1], acc[2], acc[3]);
    hp[1] = make_float4(acc[4], acc[5], acc[6], acc[7]);
}

// ---- gatherpool: (Â g_hwh + b2) summed into g_sums (pool fused) ----
__global__ void __launch_bounds__(256) k_gatherpool(const float* __restrict__ b2,
                                                    const int* __restrict__ batch) {
    int t = threadIdx.x;
    int lane = t & 31;
    int n = blockIdx.x * 32 + (t >> 3);
    int q = t & 7;
    float acc[8];
#pragma unroll
    for (int i = 0; i < 8; i++) acc[i] = 0.0f;
    int g = batch[(n < NN) ? n : (NN - 1)];
    if (n < NN) {
        int s0 = g_rowp[n], deg = g_cnti[n];
        float d = g_dis[n];
        float dd = d * d;
        float acc2[8], tmp[8];
        uint4 self = ((const uint4*)(g_hwh + (long long)n * HID))[q];
        unpack8(self, tmp);
        float4 b0 = ((const float4*)b2)[q * 2];
        float4 b1 = ((const float4*)b2)[q * 2 + 1];
        acc[0] = dd * tmp[0] + b0.x; acc[1] = dd * tmp[1] + b0.y;
        acc[2] = dd * tmp[2] + b0.z; acc[3] = dd * tmp[3] + b0.w;
        acc[4] = dd * tmp[4] + b1.x; acc[5] = dd * tmp[5] + b1.y;
        acc[6] = dd * tmp[6] + b1.z; acc[7] = dd * tmp[7] + b1.w;
#pragma unroll
        for (int i = 0; i < 8; i++) acc2[i] = 0.0f;
        int e = s0, end = s0 + deg;
        for (; e + 1 < end; e += 2) {
            uint2 e0 = g_edge[e], e1 = g_edge[e + 1];
            uint4 v0 = ((const uint4*)(g_hwh + (long long)e0.x * HID))[q];
            uint4 v1 = ((const uint4*)(g_hwh + (long long)e1.x * HID))[q];
            float f0[8], f1[8];
            unpack8(v0, f0); unpack8(v1, f1);
            float w0 = __uint_as_float(e0.y), w1 = __uint_as_float(e1.y);
#pragma unroll
            for (int i = 0; i < 8; i++) acc[i] += w0 * f0[i];
#pragma unroll
            for (int i = 0; i < 8; i++) acc2[i] += w1 * f1[i];
        }
        if (e < end) {
            uint2 e0 = g_edge[e];
            uint4 v0 = ((const uint4*)(g_hwh + (long long)e0.x * HID))[q];
            float f0[8];
            unpack8(v0, f0);
            float w0 = __uint_as_float(e0.y);
#pragma unroll
            for (int i = 0; i < 8; i++) acc[i] += w0 * f0[i];
        }
#pragma unroll
        for (int i = 0; i < 8; i++) acc[i] += acc2[i];
    }
    // pool: warp holds 4 consecutive nodes; if all share a graph, reduce
    // across nodes and issue atomics from one 8-lane group only.
    unsigned m = 0xffffffffu;
    int g0 = __shfl_sync(m, g, lane & 7);
    bool allsame = __all_sync(m, g == g0);
    if (allsame) {
#pragma unroll
        for (int i = 0; i < 8; i++) {
            acc[i] += __shfl_xor_sync(m, acc[i], 8);
            acc[i] += __shfl_xor_sync(m, acc[i], 16);
        }
        if (lane < 8) {
            float4* sp = (float4*)&g_sums[g * HID + q * 8];
            atomicAdd(sp, make_float4(acc[0], acc[1], acc[2], acc[3]));
            atomicAdd(sp + 1, make_float4(acc[4], acc[5], acc[6], acc[7]));
        }
    } else {
        float4* sp = (float4*)&g_sums[g * HID + q * 8];
        atomicAdd(sp, make_float4(acc[0], acc[1], acc[2], acc[3]));
        atomicAdd(sp + 1, make_float4(acc[4], acc[5], acc[6], acc[7]));
    }
}

// ---- final linear; counts via binary search on sorted batch ----
__global__ void k_fin(const int* __restrict__ batch,
                      const float* __restrict__ lw,
                      const float* __restrict__ lb,
                      float* __restrict__ out) {
    int g = threadIdx.x;
    if (g >= NG) return;
    // lower_bound(g) and lower_bound(g+1)
    int lo = 0, hi = NN;
    while (lo < hi) { int mid = (lo + hi) >> 1; if (batch[mid] < g) lo = mid + 1; else hi = mid; }
    int start = lo;
    lo = start; hi = NN;
    while (lo < hi) { int mid = (lo + hi) >> 1; if (batch[mid] < g + 1) lo = mid + 1; else hi = mid; }
    float cnt = (float)(lo - start);
    float inv = 1.0f / fmaxf(cnt, 1.0f);
    float acc[OC];
#pragma unroll
    for (int o = 0; o < OC; o++) acc[o] = lb[o];
    for (int k = 0; k < HID; k++) {
        float v = g_sums[g * HID + k] * inv;
#pragma unroll
        for (int o = 0; o < OC; o++) acc[o] += v * lw[k * OC + o];
    }
#pragma unroll
    for (int o = 0; o < OC; o++) out[g * OC + o] = acc[o];
}

extern "C" void kernel_launch(void* const* d_in, const int* in_sizes, int n_in,
                              void* d_out, int out_size) {
    const float* x   = (const float*)d_in[0];
    const int* ei    = (const int*)d_in[1];
    const int* bat   = (const int*)d_in[2];
    const float* W0  = (const float*)d_in[3];
    const float* b0  = (const float*)d_in[4];
    const float* W1  = (const float*)d_in[5];
    const float* b1  = (const float*)d_in[6];
    const float* W2  = (const float*)d_in[7];
    const float* b2  = (const float*)d_in[8];
    const float* lw  = (const float*)d_in[9];
    const float* lb  = (const float*)d_in[10];
    float* out       = (float*)d_out;

    const int TB = 256;
    int g32_grid = (NN + 31) / 32;
    int e8_grid = (EE / 8 + TB - 1) / TB;

    k_zero<<<(NN + TB - 1) / TB, TB>>>(x);
    k_hist<<<e8_grid, TB>>>(ei);
    k_scanA<<<(NN + 255) / 256, 256>>>();
    k_fill<<<e8_grid, TB>>>(ei);

    k_gm7<<<g32_grid, TB>>>(W0, b0);              // layer 0 -> g_h
    k_mm64<<<(NN + 63) / 64, TB>>>(W1);           // relu(g_h)@W1 -> hwh
    k_gather64h<<<g32_grid, TB>>>(b1);            // Â hwh + b1 -> g_h
    k_mm64<<<(NN + 63) / 64, TB>>>(W2);           // relu(g_h)@W2 -> hwh
    k_gatherpool<<<g32_grid, TB>>>(b2, bat);      // Â hwh + b2 -> pooled sums
    k_fin<<<1, TB>>>(bat, lw, lb, out);
}

// round 14
// speedup vs baseline: 1.6963x; 1.0387x over previous
#include <cuda_runtime.h>
#include <cuda_fp16.h>

#define NN 100000
#define EE 1200000
#define HID 64
#define NG 256
#define OC 10
#define IN0 7

// ---- scratch (static device globals) ----
__device__ int   g_cnti[NN];
__device__ int   g_rowp[NN];
__device__ int   g_cursor[NN];
__device__ int   g_total;
__device__ int   g_csr[EE];                       // src only (4B records)
__device__ float g_dis[NN];
__device__ __align__(32)  float  g_xp[NN * 8];    // dis[n]*x[n], padded to 8ch
__device__ __align__(256) __half g_hwh[NN * HID]; // prescaled fp16 rows hw' = dis*hw
__device__ float g_h[NN * HID];                   // fp32 hidden buffer (reused)
__device__ __align__(16) float g_sums[NG * HID];

// ---- histogram on dst, 4 edges/thread; spare duty: zero g_sums ----
__global__ void k_hist(const int* __restrict__ ei) {
    int tid = blockIdx.x * blockDim.x + threadIdx.x;
    if (tid < NG * HID) g_sums[tid] = 0.0f;
    if (tid == 0) g_total = 0;
    int e4 = tid * 4;
    if (e4 >= EE) return;
    int4 d = *(const int4*)&ei[EE + e4];   // EE % 4 == 0 -> aligned
    atomicAdd(&g_cnti[d.x], 1);
    atomicAdd(&g_cnti[d.y], 1);
    atomicAdd(&g_cnti[d.z], 1);
    atomicAdd(&g_cnti[d.w], 1);
}

// ---- fused scan + dis + prescaled x padding ----
__global__ void k_scanA(const float* __restrict__ x) {
    __shared__ int sm[256];
    __shared__ int base_sm;
    int t = threadIdx.x;
    int i = blockIdx.x * 256 + t;
    int v = (i < NN) ? g_cnti[i] : 0;
    sm[t] = v;
    __syncthreads();
#pragma unroll
    for (int off = 1; off < 256; off <<= 1) {
        int add = (t >= off) ? sm[t - off] : 0;
        __syncthreads();
        sm[t] += add;
        __syncthreads();
    }
    if (t == 255) base_sm = atomicAdd(&g_total, sm[255]);
    __syncthreads();
    if (i < NN) {
        int r = base_sm + sm[t] - v;
        g_rowp[i] = r;
        g_cursor[i] = r;
        float d = rsqrtf((float)v + 1.0f);
        g_dis[i] = d;
        const float* xr = x + (long long)i * IN0;
        float4 a, b;
        a.x = d * xr[0]; a.y = d * xr[1]; a.z = d * xr[2]; a.w = d * xr[3];
        b.x = d * xr[4]; b.y = d * xr[5]; b.z = d * xr[6]; b.w = 0.0f;
        ((float4*)(g_xp + (long long)i * 8))[0] = a;
        ((float4*)(g_xp + (long long)i * 8))[1] = b;
    }
}

// ---- fill CSR (src only), 4 edges/thread ----
__global__ void k_fill(const int* __restrict__ ei) {
    int e4 = (blockIdx.x * blockDim.x + threadIdx.x) * 4;
    if (e4 >= EE) return;
    int4 s = *(const int4*)&ei[e4];
    int4 d = *(const int4*)&ei[EE + e4];
    int p0 = atomicAdd(&g_cursor[d.x], 1);
    int p1 = atomicAdd(&g_cursor[d.y], 1);
    int p2 = atomicAdd(&g_cursor[d.z], 1);
    int p3 = atomicAdd(&g_cursor[d.w], 1);
    g_csr[p0] = s.x;
    g_csr[p1] = s.y;
    g_csr[p2] = s.z;
    g_csr[p3] = s.w;
}

// ---- helpers ----
__device__ __forceinline__ void unpack8(uint4 u, float* f) {
    const __half2* h = (const __half2*)&u;
#pragma unroll
    for (int j = 0; j < 4; j++) {
        float2 p = __half22float2(h[j]);
        f[2 * j] = p.x;
        f[2 * j + 1] = p.y;
    }
}

// ---- gm7: gather prescaled x + mm7(+b0) -> g_h (fp32 64ch) ----
// agg_x[n] = dis[n] * (sum_src xp'[src] + xp'[n]); h = agg_x @ W0 + b0
__global__ void __launch_bounds__(256) k_gm7(const float* __restrict__ W0,
                                             const float* __restrict__ b0) {
    __shared__ float W0s[IN0 * HID];
    __shared__ float b0s[HID];
    __shared__ float xs[32][8];
    int t = threadIdx.x;
    if (t < IN0 * 16) ((float4*)W0s)[t] = ((const float4*)W0)[t];
    if (t < 16) ((float4*)b0s)[t] = ((const float4*)b0)[t];
    int nl = t >> 3, q = t & 7;
    int n = blockIdx.x * 32 + nl;
    float val = 0.0f;
    if (n < NN) {
        int s0 = g_rowp[n], deg = g_cnti[n];
        float acc0 = g_xp[(long long)n * 8 + q];   // self (prescaled)
        float acc1 = 0.0f;
        int e = s0, end = s0 + deg;
        for (; e + 1 < end; e += 2) {
            int sa = g_csr[e], sb = g_csr[e + 1];
            acc0 += g_xp[(long long)sa * 8 + q];
            acc1 += g_xp[(long long)sb * 8 + q];
        }
        if (e < end) acc0 += g_xp[(long long)g_csr[e] * 8 + q];
        val = g_dis[n] * (acc0 + acc1);
    }
    xs[nl][q] = val;
    __syncthreads();
    if (n < NN) {
        float s[8];
#pragma unroll
        for (int i = 0; i < 8; i++) s[i] = b0s[q * 8 + i];
#pragma unroll
        for (int k = 0; k < IN0; k++) {
            float hv = xs[nl][k];
#pragma unroll
            for (int i = 0; i < 8; i++) s[i] += hv * W0s[k * HID + q * 8 + i];
        }
        float4* hp = (float4*)&g_h[(long long)n * HID + q * 8];
        hp[0] = make_float4(s[0], s[1], s[2], s[3]);
        hp[1] = make_float4(s[4], s[5], s[6], s[7]);
    }
}

// ---- mm64: g_hwh = fp16( dis[n] * (relu(g_h[n]) @ W) ), 64 nodes/block ----
__global__ void k_mm64(const float* __restrict__ W) {
    __shared__ float4 Ws4[HID * 16];    // 16 KB loaded once per 64 nodes
    __shared__ float4 hs4[16 * 16];
    int t = threadIdx.x;
#pragma unroll
    for (int i = 0; i < 4; i++) Ws4[t + 256 * i] = ((const float4*)W)[t + 256 * i];
    int nl = t >> 4;
    int q = t & 15;
#pragma unroll
    for (int g = 0; g < 4; g++) {
        int node = blockIdx.x * 64 + g * 16 + nl;
        float dn = (node < NN) ? g_dis[node] : 0.0f;
        __syncthreads();                 // covers Ws4 (g=0) and hs4 reuse
        float4 v = make_float4(0.f, 0.f, 0.f, 0.f);
        if (node < NN) v = ((const float4*)&g_h[(long long)node * HID])[q];
        v.x = fmaxf(v.x, 0.f); v.y = fmaxf(v.y, 0.f);
        v.z = fmaxf(v.z, 0.f); v.w = fmaxf(v.w, 0.f);
        hs4[nl * 16 + q] = v;
        __syncthreads();
        if (node < NN) {
            const float* hrow = (const float*)&hs4[nl * 16];
            float4 sv = make_float4(0.f, 0.f, 0.f, 0.f);
#pragma unroll
            for (int k = 0; k < HID; k++) {
                float hv = hrow[k];
                float4 w = Ws4[k * 16 + q];
                sv.x += hv * w.x; sv.y += hv * w.y; sv.z += hv * w.z; sv.w += hv * w.w;
            }
            __half2 h0 = __floats2half2_rn(dn * sv.x, dn * sv.y);
            __half2 h1 = __floats2half2_rn(dn * sv.z, dn * sv.w);
            uint2 o;
            o.x = *(unsigned*)&h0;
            o.y = *(unsigned*)&h1;
            ((uint2*)(g_hwh + (long long)node * HID))[q] = o;
        }
    }
}

// ---- gather64h: g_h = dis[n]*(sum hw'[src] + hw'[n]) + b, 8 threads/node ----
__global__ void __launch_bounds__(256) k_gather64h(const float* __restrict__ b) {
    int t = threadIdx.x;
    int n = blockIdx.x * 32 + (t >> 3);
    int q = t & 7;
    if (n >= NN) return;
    int s0 = g_rowp[n], deg = g_cnti[n];
    float acc[8], acc2[8], tmp[8];
    uint4 self = ((const uint4*)(g_hwh + (long long)n * HID))[q];
    unpack8(self, acc);                 // self term (prescaled)
#pragma unroll
    for (int i = 0; i < 8; i++) acc2[i] = 0.0f;
    int e = s0, end = s0 + deg;
    for (; e + 1 < end; e += 2) {
        int sa = g_csr[e], sb = g_csr[e + 1];
        uint4 v0 = ((const uint4*)(g_hwh + (long long)sa * HID))[q];
        uint4 v1 = ((const uint4*)(g_hwh + (long long)sb * HID))[q];
        float f0[8], f1[8];
        unpack8(v0, f0); unpack8(v1, f1);
#pragma unroll
        for (int i = 0; i < 8; i++) acc[i] += f0[i];
#pragma unroll
        for (int i = 0; i < 8; i++) acc2[i] += f1[i];
    }
    if (e < end) {
        uint4 v0 = ((const uint4*)(g_hwh + (long long)g_csr[e] * HID))[q];
        unpack8(v0, tmp);
#pragma unroll
        for (int i = 0; i < 8; i++) acc[i] += tmp[i];
    }
    float dn = g_dis[n];
    float4 b0 = ((const float4*)b)[q * 2];
    float4 b1 = ((const float4*)b)[q * 2 + 1];
    float r[8];
    r[0] = dn * (acc[0] + acc2[0]) + b0.x; r[1] = dn * (acc[1] + acc2[1]) + b0.y;
    r[2] = dn * (acc[2] + acc2[2]) + b0.z; r[3] = dn * (acc[3] + acc2[3]) + b0.w;
    r[4] = dn * (acc[4] + acc2[4]) + b1.x; r[5] = dn * (acc[5] + acc2[5]) + b1.y;
    r[6] = dn * (acc[6] + acc2[6]) + b1.z; r[7] = dn * (acc[7] + acc2[7]) + b1.w;
    float4* hp = (float4*)&g_h[(long long)n * HID + q * 8];
    hp[0] = make_float4(r[0], r[1], r[2], r[3]);
    hp[1] = make_float4(r[4], r[5], r[6], r[7]);
}

// ---- gatherpool: (dis[n]*(sum hw'+self') + b2) pooled into g_sums ----
__global__ void __launch_bounds__(256) k_gatherpool(const float* __restrict__ b2,
                                                    const int* __restrict__ batch) {
    int t = threadIdx.x;
    int lane = t & 31;
    int n = blockIdx.x * 32 + (t >> 3);
    int q = t & 7;
    float r[8];
#pragma unroll
    for (int i = 0; i < 8; i++) r[i] = 0.0f;
    int g = batch[(n < NN) ? n : (NN - 1)];
    if (n < NN) {
        int s0 = g_rowp[n], deg = g_cnti[n];
        float acc[8], acc2[8], tmp[8];
        uint4 self = ((const uint4*)(g_hwh + (long long)n * HID))[q];
        unpack8(self, acc);
#pragma unroll
        for (int i = 0; i < 8; i++) acc2[i] = 0.0f;
        int e = s0, end = s0 + deg;
        for (; e + 1 < end; e += 2) {
            int sa = g_csr[e], sb = g_csr[e + 1];
            uint4 v0 = ((const uint4*)(g_hwh + (long long)sa * HID))[q];
            uint4 v1 = ((const uint4*)(g_hwh + (long long)sb * HID))[q];
            float f0[8], f1[8];
            unpack8(v0, f0); unpack8(v1, f1);
#pragma unroll
            for (int i = 0; i < 8; i++) acc[i] += f0[i];
#pragma unroll
            for (int i = 0; i < 8; i++) acc2[i] += f1[i];
        }
        if (e < end) {
            uint4 v0 = ((const uint4*)(g_hwh + (long long)g_csr[e] * HID))[q];
            unpack8(v0, tmp);
#pragma unroll
            for (int i = 0; i < 8; i++) acc[i] += tmp[i];
        }
        float dn = g_dis[n];
        float4 b0 = ((const float4*)b2)[q * 2];
        float4 b1 = ((const float4*)b2)[q * 2 + 1];
        r[0] = dn * (acc[0] + acc2[0]) + b0.x; r[1] = dn * (acc[1] + acc2[1]) + b0.y;
        r[2] = dn * (acc[2] + acc2[2]) + b0.z; r[3] = dn * (acc[3] + acc2[3]) + b0.w;
        r[4] = dn * (acc[4] + acc2[4]) + b1.x; r[5] = dn * (acc[5] + acc2[5]) + b1.y;
        r[6] = dn * (acc[6] + acc2[6]) + b1.z; r[7] = dn * (acc[7] + acc2[7]) + b1.w;
    }
    // pool: warp holds 4 consecutive nodes; if all share a graph, reduce
    // across nodes and issue atomics from one 8-lane group only.
    unsigned m = 0xffffffffu;
    int g0 = __shfl_sync(m, g, lane & 7);
    bool allsame = __all_sync(m, g == g0);
    if (allsame) {
#pragma unroll
        for (int i = 0; i < 8; i++) {
            r[i] += __shfl_xor_sync(m, r[i], 8);
            r[i] += __shfl_xor_sync(m, r[i], 16);
        }
        if (lane < 8) {
            float4* sp = (float4*)&g_sums[g * HID + q * 8];
            atomicAdd(sp, make_float4(r[0], r[1], r[2], r[3]));
            atomicAdd(sp + 1, make_float4(r[4], r[5], r[6], r[7]));
        }
    } else {
        float4* sp = (float4*)&g_sums[g * HID + q * 8];
        atomicAdd(sp, make_float4(r[0], r[1], r[2], r[3]));
        atomicAdd(sp + 1, make_float4(r[4], r[5], r[6], r[7]));
    }
}

// ---- final linear; counts via binary search on sorted batch ----
__global__ void k_fin(const int* __restrict__ batch,
                      const float* __restrict__ lw,
                      const float* __restrict__ lb,
                      float* __restrict__ out) {
    int g = threadIdx.x;
    if (g >= NG) return;
    int lo = 0, hi = NN;
    while (lo < hi) { int mid = (lo + hi) >> 1; if (batch[mid] < g) lo = mid + 1; else hi = mid; }
    int start = lo;
    lo = start; hi = NN;
    while (lo < hi) { int mid = (lo + hi) >> 1; if (batch[mid] < g + 1) lo = mid + 1; else hi = mid; }
    float cnt = (float)(lo - start);
    float inv = 1.0f / fmaxf(cnt, 1.0f);
    float acc[OC];
#pragma unroll
    for (int o = 0; o < OC; o++) acc[o] = lb[o];
    for (int k = 0; k < HID; k++) {
        float v = g_sums[g * HID + k] * inv;
#pragma unroll
        for (int o = 0; o < OC; o++) acc[o] += v * lw[k * OC + o];
    }
#pragma unroll
    for (int o = 0; o < OC; o++) out[g * OC + o] = acc[o];
}

extern "C" void kernel_launch(void* const* d_in, const int* in_sizes, int n_in,
                              void* d_out, int out_size) {
    const float* x   = (const float*)d_in[0];
    const int* ei    = (const int*)d_in[1];
    const int* bat   = (const int*)d_in[2];
    const float* W0  = (const float*)d_in[3];
    const float* b0  = (const float*)d_in[4];
    const float* W1  = (const float*)d_in[5];
    const float* b1  = (const float*)d_in[6];
    const float* W2  = (const float*)d_in[7];
    const float* b2  = (const float*)d_in[8];
    const float* lw  = (const float*)d_in[9];
    const float* lb  = (const float*)d_in[10];
    float* out       = (float*)d_out;

    const int TB = 256;
    int g32_grid = (NN + 31) / 32;
    int e4_grid = (EE / 4 + TB - 1) / TB;

    // zero degree counters (graph-capturable async memset; no allocation)
    int* cnti_ptr = nullptr;
    cudaGetSymbolAddress((void**)&cnti_ptr, g_cnti);
    cudaMemsetAsync(cnti_ptr, 0, NN * sizeof(int));

    k_hist<<<e4_grid, TB>>>(ei);                  // hist + zero g_sums/g_total
    k_scanA<<<(NN + 255) / 256, 256>>>(x);        // scan + dis + prescaled xp
    k_fill<<<e4_grid, TB>>>(ei);                  // src-only CSR

    k_gm7<<<g32_grid, TB>>>(W0, b0);              // layer 0 -> g_h
    k_mm64<<<(NN + 63) / 64, TB>>>(W1);           // dis*(relu(g_h)@W1) -> hwh
    k_gather64h<<<g32_grid, TB>>>(b1);            // gather -> g_h
    k_mm64<<<(NN + 63) / 64, TB>>>(W2);           // dis*(relu(g_h)@W2) -> hwh
    k_gatherpool<<<g32_grid, TB>>>(b2, bat);      // gather + pool -> sums
    k_fin<<<1, TB>>>(bat, lw, lb, out);
}